// round 13
// baseline (speedup 1.0000x reference)
#include <cuda_runtime.h>
#include <cuda_bf16.h>
#include <cstdint>

// Fused GCA step via warp-level bf16 mma.sync; row-pair tiles,
// channel-split 4-row perception, k-split layer-2 (acc->A reuse),
// ch-pair-packed bf16 ds partials (sts32), pipelined ldsm.
// B=16,C=16,H=256,W=256, HID=128, OUT_C=13, perception K=48.
#define Cz     16
#define HID    128
#define OUTC   13
#define NPAIRS 2048
#define TPB    256
#define GRID   296
#define PCH    48

// ---- shared memory (bytes) ----
#define SM_PA  0            // P_A[48][256] bf16 swizzled 512B rows -> 24576
#define SM_PB  24576        // P_B                                   -> 24576
#define SM_DS  49152        // ds partials [4 kg][8 chpair][256 px] u32 -> 32768
#define SM_TOT 81920
// one-time weight staging overlaps DS (consumed before first DS write)
#define SM_W1T (SM_DS)              // W1t[48][128] bf16 256B rows (12288)
#define SM_W2T (SM_DS + 12288)      // W2t[128][16] bf16 32B rows   (4096)

typedef unsigned int u32;

__device__ __forceinline__ u32 smem_u32(const void* p) {
    u32 a;
    asm("{ .reg .u64 t; cvta.to.shared.u64 t, %1; cvt.u32.u64 %0, t; }"
        : "=r"(a) : "l"(p));
    return a;
}
__device__ __forceinline__ u32 bf2(float lo, float hi) {
    u32 r;  // first asm src -> upper half
    asm("cvt.rn.bf16x2.f32 %0, %1, %2;" : "=r"(r) : "f"(hi), "f"(lo));
    return r;
}
__device__ __forceinline__ void sts32(u32 a, u32 v) {
    asm volatile("st.shared.b32 [%0], %1;" :: "r"(a), "r"(v) : "memory");
}
__device__ __forceinline__ uint2 lds64u(u32 a) {
    uint2 r;
    asm volatile("ld.shared.v2.b32 {%0,%1}, [%2];" : "=r"(r.x), "=r"(r.y) : "r"(a));
    return r;
}
__device__ __forceinline__ void ldsm4t(u32* r, u32 a) {
    asm volatile("ldmatrix.sync.aligned.m8n8.x4.trans.shared.b16 {%0,%1,%2,%3}, [%4];"
        : "=r"(r[0]), "=r"(r[1]), "=r"(r[2]), "=r"(r[3]) : "r"(a));
}
__device__ __forceinline__ void ldsm2t(u32* r, u32 a) {
    asm volatile("ldmatrix.sync.aligned.m8n8.x2.trans.shared.b16 {%0,%1}, [%2];"
        : "=r"(r[0]), "=r"(r[1]) : "r"(a));
}
__device__ __forceinline__ void mma16816(float* d, const u32* a, const u32* b) {
    asm volatile(
        "mma.sync.aligned.m16n8k16.row.col.f32.bf16.bf16.f32 "
        "{%0,%1,%2,%3}, {%4,%5,%6,%7}, {%8,%9}, {%0,%1,%2,%3};"
        : "+f"(d[0]), "+f"(d[1]), "+f"(d[2]), "+f"(d[3])
        : "r"(a[0]), "r"(a[1]), "r"(a[2]), "r"(a[3]), "r"(b[0]), "r"(b[1]));
}

// P: bf16 [rows][256 px], 512B rows, XOR-swizzled 16B groups
__device__ __forceinline__ u32 p_off(int row, int px) {
    return (u32)(row * 512 + ((((px) >> 3) ^ (row & 7)) << 4) + ((px & 7) << 1));
}
// ds: u32 [4 kg][8 chpair][256 px]; bank-rotate by chpair
__device__ __forceinline__ u32 dsc_off(int cp, int px) {
    return (u32)(cp * 1024 + (((px) << 2) ^ ((cp & 7) << 5)));
}

__global__ __launch_bounds__(TPB, 2)
void GCA_mma5_kernel(const float* __restrict__ in, const float* __restrict__ w1,
                     const float* __restrict__ b1, const float* __restrict__ w2,
                     float* __restrict__ out)
{
    extern __shared__ char smem[];
    const u32 sb = smem_u32(smem);
    const int tid  = threadIdx.x;
    const int wid  = tid >> 5;
    const int lane = tid & 31;
    const int q    = lane & 3;
    const int kg   = wid & 3;          // hidden k-group: cols 32*kg..32*kg+31
    const int wpx  = wid >> 2;         // px half within the row

    // ---- stage transposed bf16 weights (overlaps DS; one-time) ----
    for (int i = tid; i < HID * PCH; i += TPB) {
        int n = i / PCH, k = i - n * PCH;
        *reinterpret_cast<__nv_bfloat16*>(smem + SM_W1T + k * 256 + n * 2) =
            __float2bfloat16(w1[i]);
    }
    for (int i = tid; i < HID * 16; i += TPB) {
        int k = i >> 4, n = i & 15;
        float v = (n < OUTC) ? w2[n * HID + k] : 0.0f;
        *reinterpret_cast<__nv_bfloat16*>(smem + SM_W2T + i * 2) =
            __float2bfloat16(v);
    }
    __syncthreads();

    // ---- persistent weight fragments + bias (per warp k-group) ----
    u32 fb1[4][3][2];
    u32 fb2[2][2][2];
    float bias[4][2];
#pragma unroll
    for (int j = 0; j < 4; ++j) {
#pragma unroll
        for (int kk = 0; kk < 3; ++kk)
            ldsm2t(fb1[j][kk],
                   sb + SM_W1T + (16 * kk + (lane & 15)) * 256 + (32 * kg + 8 * j) * 2);
        bias[j][0] = b1[32 * kg + 8 * j + 2 * q];
        bias[j][1] = b1[32 * kg + 8 * j + 2 * q + 1];
    }
#pragma unroll
    for (int kb = 0; kb < 2; ++kb)
#pragma unroll
        for (int n2 = 0; n2 < 2; ++n2)
            ldsm2t(fb2[kb][n2],
                   sb + SM_W2T + (32 * kg + 16 * kb + (lane & 15)) * 32 + 8 * n2 * 2);
    __syncthreads();      // weights consumed; DS region free

    const int lk = (lane & 7) + ((lane >> 4) << 3);
    const int lm = ((lane >> 3) & 1) << 3;
    const int l4 = lane >> 2;

    for (int pair = blockIdx.x; pair < NPAIRS; pair += GRID) {
        const int bimg = pair >> 7;
        const int y0   = (pair & 127) << 1;
        const float* bbase = in + ((size_t)bimg << 20);
        float* obase = out + ((size_t)bimg << 20);

        // ===== phase 1: perception — ch-split, 4 input rows, both outputs =====
        {
            const int cg = tid >> 7;               // 0: ch 0-7, 1: ch 8-15
            const int x0 = (tid & 127) << 1;       // even, +1 never wraps
            const int xm = (x0 - 1) & 255, x2 = (x0 + 2) & 255;
            const int rA = ((y0 - 1) & 255) << 8;
            const int rB = y0 << 8;
            const int rC = (y0 + 1) << 8;
            const int rD = ((y0 + 2) & 255) << 8;
#pragma unroll
            for (int c8 = 0; c8 < 8; ++c8) {
                const int ch = cg * 8 + c8;
                const float* pc = bbase + (ch << 16);
                float2 vA = *reinterpret_cast<const float2*>(pc + rA + x0);
                float2 vB = *reinterpret_cast<const float2*>(pc + rB + x0);
                float2 vC = *reinterpret_cast<const float2*>(pc + rC + x0);
                float2 vD = *reinterpret_cast<const float2*>(pc + rD + x0);
                float aL = pc[rA + xm], aR = pc[rA + x2];
                float bL = pc[rB + xm], bR = pc[rB + x2];
                float cL = pc[rC + xm], cR = pc[rC + x2];
                float dL = pc[rD + xm], dR = pc[rD + x2];

                float gx0 = (vA.y - aL) + 2.0f * (vB.y - bL) + (vC.y - cL);
                float gx1 = (aR - vA.x) + 2.0f * (bR - vB.x) + (cR - vC.x);
                float gy0 = (cL + 2.0f * vC.x + vC.y) - (aL + 2.0f * vA.x + vA.y);
                float gy1 = (vC.x + 2.0f * vC.y + cR) - (vA.x + 2.0f * vA.y + aR);
                sts32(sb + SM_PA + p_off(ch,          x0), bf2(vB.x, vB.y));
                sts32(sb + SM_PA + p_off(Cz + ch,     x0), bf2(gx0, gx1));
                sts32(sb + SM_PA + p_off(2 * Cz + ch, x0), bf2(gy0, gy1));

                float hx0 = (vB.y - bL) + 2.0f * (vC.y - cL) + (vD.y - dL);
                float hx1 = (bR - vB.x) + 2.0f * (cR - vC.x) + (dR - vD.x);
                float hy0 = (dL + 2.0f * vD.x + vD.y) - (bL + 2.0f * vB.x + vB.y);
                float hy1 = (vD.x + 2.0f * vD.y + dR) - (vB.x + 2.0f * vB.y + bR);
                sts32(sb + SM_PB + p_off(ch,          x0), bf2(vC.x, vC.y));
                sts32(sb + SM_PB + p_off(Cz + ch,     x0), bf2(hx0, hx1));
                sts32(sb + SM_PB + p_off(2 * Cz + ch, x0), bf2(hy0, hy1));

                if (ch < 3) {                      // exact state copy, both rows
                    *reinterpret_cast<float2*>(obase + (ch << 16) + rB + x0) = vB;
                    *reinterpret_cast<float2*>(obase + (ch << 16) + rC + x0) = vC;
                }
            }
        }
        __syncthreads();

        // ===== phases 2-4 for each row of the pair =====
#pragma unroll 1
        for (int rs = 0; rs < 2; ++rs) {
            const u32 pb = sb + (rs ? SM_PB : SM_PA);
            const int r0 = (y0 + rs) << 8;

            // ---- fused MLP, k-split layer-2, pipelined ldsm ----
            u32 aA[3][4], aB[3][4];
            {
                const int pxc = 128 * wpx + lm;
#pragma unroll
                for (int kk = 0; kk < 3; ++kk) {
                    int krow = 16 * kk + lk;
                    ldsm4t(aA[kk], pb + (u32)(krow * 512 +
                           (((pxc >> 3) ^ (krow & 7)) << 4)));
                }
            }
#pragma unroll 1
            for (int mt = 0; mt < 8; ++mt) {
                const int pxb = 128 * wpx + 16 * mt;
                u32 (*ac)[4] = (mt & 1) ? aB : aA;
                u32 (*an)[4] = (mt & 1) ? aA : aB;

                // layer-1: 4 n-tiles -> bias+ReLU -> bf16 A-frags
                u32 a2f[2][4];
#pragma unroll
                for (int j = 0; j < 4; ++j) {
                    float c[4] = {0.f, 0.f, 0.f, 0.f};
#pragma unroll
                    for (int kk = 0; kk < 3; ++kk) mma16816(c, ac[kk], fb1[j][kk]);
                    float h0 = fmaxf(c[0] + bias[j][0], 0.f);
                    float h1 = fmaxf(c[1] + bias[j][1], 0.f);
                    float h2 = fmaxf(c[2] + bias[j][0], 0.f);
                    float h3 = fmaxf(c[3] + bias[j][1], 0.f);
                    a2f[j >> 1][(j & 1) * 2]     = bf2(h0, h1);
                    a2f[j >> 1][(j & 1) * 2 + 1] = bf2(h2, h3);
                }

                // prefetch next mt's A-frags (latency hides under layer-2)
                if (mt < 7) {
                    const int pxc = pxb + 16 + lm;
#pragma unroll
                    for (int kk = 0; kk < 3; ++kk) {
                        int krow = 16 * kk + lk;
                        ldsm4t(an[kk], pb + (u32)(krow * 512 +
                               (((pxc >> 3) ^ (krow & 7)) << 4)));
                    }
                }

                // layer-2 partial over this warp's 32 hidden channels
                float c2[2][4] = {{0.f,0.f,0.f,0.f},{0.f,0.f,0.f,0.f}};
#pragma unroll
                for (int kb = 0; kb < 2; ++kb) {
                    mma16816(c2[0], a2f[kb], fb2[kb][0]);
                    mma16816(c2[1], a2f[kb], fb2[kb][1]);
                }

                // ds partial: ch-pair packed bf16x2, 4 sts32
                const u32 dsb = sb + SM_DS + (u32)kg * 8192u;
#pragma unroll
                for (int n2 = 0; n2 < 2; ++n2) {
                    const int cp = 4 * n2 + q;
#pragma unroll
                    for (int hf = 0; hf < 2; ++hf) {
                        int px = pxb + hf * 8 + l4;
                        sts32(dsb + dsc_off(cp, px),
                              bf2(c2[n2][hf * 2], c2[n2][hf * 2 + 1]));
                    }
                }
            }
            __syncthreads();

            // ---- reduce 4 kg partials (ch-pair words) + residual ----
            {
                const int px0 = (tid & 127) << 1;
                const int cpa = (tid < 128) ? 0 : 4;
                const int cpe = (tid < 128) ? 4 : 7;
                for (int cp = cpa; cp < cpe; ++cp) {
                    const int chL = 3 + 2 * cp;         // 3,5,..,15
                    const int chH = chL + 1;            // 4,6,..,16(skip)
                    float2 sL = *reinterpret_cast<const float2*>(
                        bbase + (chL << 16) + r0 + px0);
                    float2 sH = make_float2(0.f, 0.f);
                    if (chH < 16)
                        sH = *reinterpret_cast<const float2*>(
                            bbase + (chH << 16) + r0 + px0);
                    const u32 base = sb + SM_DS + dsc_off(cp, px0);
#pragma unroll
                    for (int g = 0; g < 4; ++g) {
                        uint2 w = lds64u(base + (u32)g * 8192u);
                        sL.x += __uint_as_float(w.x << 16);
                        sH.x += __uint_as_float(w.x & 0xFFFF0000u);
                        sL.y += __uint_as_float(w.y << 16);
                        sH.y += __uint_as_float(w.y & 0xFFFF0000u);
                    }
                    *reinterpret_cast<float2*>(obase + (chL << 16) + r0 + px0) = sL;
                    if (chH < 16)
                        *reinterpret_cast<float2*>(
                            obase + (chH << 16) + r0 + px0) = sH;
                }
            }
            __syncthreads();
        }
    }
}

extern "C" void kernel_launch(void* const* d_in, const int* in_sizes, int n_in,
                              void* d_out, int out_size)
{
    const float* in = (const float*)d_in[0];
    const float* w1 = (const float*)d_in[1];
    const float* b1 = (const float*)d_in[2];
    const float* w2 = (const float*)d_in[3];
    float* out = (float*)d_out;

    cudaFuncSetAttribute(GCA_mma5_kernel,
                         cudaFuncAttributeMaxDynamicSharedMemorySize, SM_TOT);
    GCA_mma5_kernel<<<GRID, TPB, SM_TOT>>>(in, w1, b1, w2, out);
}

// round 15
// speedup vs baseline: 1.1730x; 1.1730x over previous
#include <cuda_runtime.h>
#include <cuda_bf16.h>
#include <cstdint>

// Fused GCA step via warp-level bf16 mma.sync; row-pair tiles,
// channel-split 4-row perception, k-split layer-2 (acc->A reuse),
// ch-pair-packed bf16x2 ds partials (sts32), ch-pair reduce.
// B=16,C=16,H=256,W=256, HID=128, OUT_C=13, perception K=48.
#define Cz     16
#define HID    128
#define OUTC   13
#define NPAIRS 2048
#define TPB    256
#define GRID   296
#define PCH    48

// ---- shared memory (bytes) ----
#define SM_PA  0            // P_A[48][256] bf16 swizzled 512B rows -> 24576
#define SM_PB  24576        // P_B                                   -> 24576
#define SM_DS  49152        // ds partials [4 kg][8 chpair][256 px] u32 -> 32768
#define SM_TOT 81920
// one-time weight staging overlaps DS (consumed before first DS write)
#define SM_W1T (SM_DS)              // W1t[48][128] bf16 256B rows (12288)
#define SM_W2T (SM_DS + 12288)      // W2t[128][16] bf16 32B rows   (4096)

typedef unsigned int u32;

__device__ __forceinline__ u32 smem_u32(const void* p) {
    u32 a;
    asm("{ .reg .u64 t; cvta.to.shared.u64 t, %1; cvt.u32.u64 %0, t; }"
        : "=r"(a) : "l"(p));
    return a;
}
__device__ __forceinline__ u32 bf2(float lo, float hi) {
    u32 r;  // first asm src -> upper half
    asm("cvt.rn.bf16x2.f32 %0, %1, %2;" : "=r"(r) : "f"(hi), "f"(lo));
    return r;
}
__device__ __forceinline__ void sts32(u32 a, u32 v) {
    asm volatile("st.shared.b32 [%0], %1;" :: "r"(a), "r"(v) : "memory");
}
__device__ __forceinline__ uint2 lds64u(u32 a) {
    uint2 r;
    asm volatile("ld.shared.v2.b32 {%0,%1}, [%2];" : "=r"(r.x), "=r"(r.y) : "r"(a));
    return r;
}
__device__ __forceinline__ void ldsm4t(u32* r, u32 a) {
    asm volatile("ldmatrix.sync.aligned.m8n8.x4.trans.shared.b16 {%0,%1,%2,%3}, [%4];"
        : "=r"(r[0]), "=r"(r[1]), "=r"(r[2]), "=r"(r[3]) : "r"(a));
}
__device__ __forceinline__ void ldsm2t(u32* r, u32 a) {
    asm volatile("ldmatrix.sync.aligned.m8n8.x2.trans.shared.b16 {%0,%1}, [%2];"
        : "=r"(r[0]), "=r"(r[1]) : "r"(a));
}
__device__ __forceinline__ void mma16816(float* d, const u32* a, const u32* b) {
    asm volatile(
        "mma.sync.aligned.m16n8k16.row.col.f32.bf16.bf16.f32 "
        "{%0,%1,%2,%3}, {%4,%5,%6,%7}, {%8,%9}, {%0,%1,%2,%3};"
        : "+f"(d[0]), "+f"(d[1]), "+f"(d[2]), "+f"(d[3])
        : "r"(a[0]), "r"(a[1]), "r"(a[2]), "r"(a[3]), "r"(b[0]), "r"(b[1]));
}

// P: bf16 [rows][256 px], 512B rows, XOR-swizzled 16B groups
__device__ __forceinline__ u32 p_off(int row, int px) {
    return (u32)(row * 512 + ((((px) >> 3) ^ (row & 7)) << 4) + ((px & 7) << 1));
}
// ds: u32 [4 kg][8 chpair][256 px]; bank-rotate by chpair
__device__ __forceinline__ u32 dsc_off(int cp, int px) {
    return (u32)(cp * 1024 + (((px) << 2) ^ ((cp & 7) << 5)));
}

__global__ __launch_bounds__(TPB, 2)
void GCA_mma6_kernel(const float* __restrict__ in, const float* __restrict__ w1,
                     const float* __restrict__ b1, const float* __restrict__ w2,
                     float* __restrict__ out)
{
    extern __shared__ char smem[];
    const u32 sb = smem_u32(smem);
    const int tid  = threadIdx.x;
    const int wid  = tid >> 5;
    const int lane = tid & 31;
    const int q    = lane & 3;
    const int kg   = wid & 3;          // hidden k-group: cols 32*kg..32*kg+31
    const int wpx  = wid >> 2;         // px half within the row

    // ---- stage transposed bf16 weights (overlaps DS; one-time) ----
    for (int i = tid; i < HID * PCH; i += TPB) {
        int n = i / PCH, k = i - n * PCH;
        *reinterpret_cast<__nv_bfloat16*>(smem + SM_W1T + k * 256 + n * 2) =
            __float2bfloat16(w1[i]);
    }
    for (int i = tid; i < HID * 16; i += TPB) {
        int k = i >> 4, n = i & 15;
        float v = (n < OUTC) ? w2[n * HID + k] : 0.0f;
        *reinterpret_cast<__nv_bfloat16*>(smem + SM_W2T + i * 2) =
            __float2bfloat16(v);
    }
    __syncthreads();

    // ---- persistent weight fragments + bias (per warp k-group) ----
    u32 fb1[4][3][2];
    u32 fb2[2][2][2];
    float bias[4][2];
#pragma unroll
    for (int j = 0; j < 4; ++j) {
#pragma unroll
        for (int kk = 0; kk < 3; ++kk)
            ldsm2t(fb1[j][kk],
                   sb + SM_W1T + (16 * kk + (lane & 15)) * 256 + (32 * kg + 8 * j) * 2);
        bias[j][0] = b1[32 * kg + 8 * j + 2 * q];
        bias[j][1] = b1[32 * kg + 8 * j + 2 * q + 1];
    }
#pragma unroll
    for (int kb = 0; kb < 2; ++kb)
#pragma unroll
        for (int n2 = 0; n2 < 2; ++n2)
            ldsm2t(fb2[kb][n2],
                   sb + SM_W2T + (32 * kg + 16 * kb + (lane & 15)) * 32 + 8 * n2 * 2);
    __syncthreads();      // weights consumed; DS region free

    const int lk = (lane & 7) + ((lane >> 4) << 3);
    const int lm = ((lane >> 3) & 1) << 3;
    const int l4 = lane >> 2;

    for (int pair = blockIdx.x; pair < NPAIRS; pair += GRID) {
        const int bimg = pair >> 7;
        const int y0   = (pair & 127) << 1;
        const float* bbase = in + ((size_t)bimg << 20);
        float* obase = out + ((size_t)bimg << 20);

        // ===== phase 1: perception — ch-split, 4 input rows, both outputs =====
        {
            const int cg = tid >> 7;               // 0: ch 0-7, 1: ch 8-15
            const int x0 = (tid & 127) << 1;       // even, +1 never wraps
            const int xm = (x0 - 1) & 255, x2 = (x0 + 2) & 255;
            const int rA = ((y0 - 1) & 255) << 8;
            const int rB = y0 << 8;
            const int rC = (y0 + 1) << 8;
            const int rD = ((y0 + 2) & 255) << 8;
#pragma unroll
            for (int c8 = 0; c8 < 8; ++c8) {
                const int ch = cg * 8 + c8;
                const float* pc = bbase + (ch << 16);
                float2 vA = *reinterpret_cast<const float2*>(pc + rA + x0);
                float2 vB = *reinterpret_cast<const float2*>(pc + rB + x0);
                float2 vC = *reinterpret_cast<const float2*>(pc + rC + x0);
                float2 vD = *reinterpret_cast<const float2*>(pc + rD + x0);
                float aL = pc[rA + xm], aR = pc[rA + x2];
                float bL = pc[rB + xm], bR = pc[rB + x2];
                float cL = pc[rC + xm], cR = pc[rC + x2];
                float dL = pc[rD + xm], dR = pc[rD + x2];

                float gx0 = (vA.y - aL) + 2.0f * (vB.y - bL) + (vC.y - cL);
                float gx1 = (aR - vA.x) + 2.0f * (bR - vB.x) + (cR - vC.x);
                float gy0 = (cL + 2.0f * vC.x + vC.y) - (aL + 2.0f * vA.x + vA.y);
                float gy1 = (vC.x + 2.0f * vC.y + cR) - (vA.x + 2.0f * vA.y + aR);
                sts32(sb + SM_PA + p_off(ch,          x0), bf2(vB.x, vB.y));
                sts32(sb + SM_PA + p_off(Cz + ch,     x0), bf2(gx0, gx1));
                sts32(sb + SM_PA + p_off(2 * Cz + ch, x0), bf2(gy0, gy1));

                float hx0 = (vB.y - bL) + 2.0f * (vC.y - cL) + (vD.y - dL);
                float hx1 = (bR - vB.x) + 2.0f * (cR - vC.x) + (dR - vD.x);
                float hy0 = (dL + 2.0f * vD.x + vD.y) - (bL + 2.0f * vB.x + vB.y);
                float hy1 = (vD.x + 2.0f * vD.y + dR) - (vB.x + 2.0f * vB.y + bR);
                sts32(sb + SM_PB + p_off(ch,          x0), bf2(vC.x, vC.y));
                sts32(sb + SM_PB + p_off(Cz + ch,     x0), bf2(hx0, hx1));
                sts32(sb + SM_PB + p_off(2 * Cz + ch, x0), bf2(hy0, hy1));

                if (ch < 3) {                      // exact state copy, both rows
                    *reinterpret_cast<float2*>(obase + (ch << 16) + rB + x0) = vB;
                    *reinterpret_cast<float2*>(obase + (ch << 16) + rC + x0) = vC;
                }
            }
        }
        __syncthreads();

        // ===== phases 2-4 for each row of the pair =====
#pragma unroll 1
        for (int rs = 0; rs < 2; ++rs) {
            const u32 pb = sb + (rs ? SM_PB : SM_PA);
            const int r0 = (y0 + rs) << 8;

            // ---- fused MLP, k-split layer-2 ----
#pragma unroll 1
            for (int mt = 0; mt < 8; ++mt) {
                const int pxb = 128 * wpx + 16 * mt;
                u32 a[3][4];
#pragma unroll
                for (int kk = 0; kk < 3; ++kk) {
                    int krow = 16 * kk + lk;
                    int pxc  = pxb + lm;
                    ldsm4t(a[kk], pb + (u32)(krow * 512 +
                           (((pxc >> 3) ^ (krow & 7)) << 4)));
                }

                // layer-1: 4 n-tiles -> bias+ReLU -> bf16 A-frags
                u32 a2f[2][4];
#pragma unroll
                for (int j = 0; j < 4; ++j) {
                    float c[4] = {0.f, 0.f, 0.f, 0.f};
#pragma unroll
                    for (int kk = 0; kk < 3; ++kk) mma16816(c, a[kk], fb1[j][kk]);
                    float h0 = fmaxf(c[0] + bias[j][0], 0.f);
                    float h1 = fmaxf(c[1] + bias[j][1], 0.f);
                    float h2 = fmaxf(c[2] + bias[j][0], 0.f);
                    float h3 = fmaxf(c[3] + bias[j][1], 0.f);
                    a2f[j >> 1][(j & 1) * 2]     = bf2(h0, h1);
                    a2f[j >> 1][(j & 1) * 2 + 1] = bf2(h2, h3);
                }

                // layer-2 partial over this warp's 32 hidden channels
                float c2[2][4] = {{0.f,0.f,0.f,0.f},{0.f,0.f,0.f,0.f}};
#pragma unroll
                for (int kb = 0; kb < 2; ++kb) {
                    mma16816(c2[0], a2f[kb], fb2[kb][0]);
                    mma16816(c2[1], a2f[kb], fb2[kb][1]);
                }

                // ds partial: ch-pair packed bf16x2, 4 sts32
                const u32 dsb = sb + SM_DS + (u32)kg * 8192u;
#pragma unroll
                for (int n2 = 0; n2 < 2; ++n2) {
                    const int cp = 4 * n2 + q;
#pragma unroll
                    for (int hf = 0; hf < 2; ++hf) {
                        int px = pxb + hf * 8 + l4;
                        sts32(dsb + dsc_off(cp, px),
                              bf2(c2[n2][hf * 2], c2[n2][hf * 2 + 1]));
                    }
                }
            }
            __syncthreads();

            // ---- reduce 4 kg partials (ch-pair words) + residual ----
            {
                const int px0 = (tid & 127) << 1;
                const int cpa = (tid < 128) ? 0 : 4;
                const int cpe = (tid < 128) ? 4 : 7;
                for (int cp = cpa; cp < cpe; ++cp) {
                    const int chL = 3 + 2 * cp;         // 3,5,..,15
                    const int chH = chL + 1;
                    float2 sL = *reinterpret_cast<const float2*>(
                        bbase + (chL << 16) + r0 + px0);
                    float2 sH = make_float2(0.f, 0.f);
                    if (chH < 16)
                        sH = *reinterpret_cast<const float2*>(
                            bbase + (chH << 16) + r0 + px0);
                    const u32 base = sb + SM_DS + dsc_off(cp, px0);
#pragma unroll
                    for (int g = 0; g < 4; ++g) {
                        uint2 w = lds64u(base + (u32)g * 8192u);
                        sL.x += __uint_as_float(w.x << 16);
                        sH.x += __uint_as_float(w.x & 0xFFFF0000u);
                        sL.y += __uint_as_float(w.y << 16);
                        sH.y += __uint_as_float(w.y & 0xFFFF0000u);
                    }
                    *reinterpret_cast<float2*>(obase + (chL << 16) + r0 + px0) = sL;
                    if (chH < 16)
                        *reinterpret_cast<float2*>(
                            obase + (chH << 16) + r0 + px0) = sH;
                }
            }
            __syncthreads();
        }
    }
}

extern "C" void kernel_launch(void* const* d_in, const int* in_sizes, int n_in,
                              void* d_out, int out_size)
{
    const float* in = (const float*)d_in[0];
    const float* w1 = (const float*)d_in[1];
    const float* b1 = (const float*)d_in[2];
    const float* w2 = (const float*)d_in[3];
    float* out = (float*)d_out;

    cudaFuncSetAttribute(GCA_mma6_kernel,
                         cudaFuncAttributeMaxDynamicSharedMemorySize, SM_TOT);
    GCA_mma6_kernel<<<GRID, TPB, SM_TOT>>>(in, w1, b1, w2, out);
}

// round 16
// speedup vs baseline: 1.1991x; 1.0222x over previous
#include <cuda_runtime.h>
#include <cuda_bf16.h>
#include <cstdint>

// Fused GCA step via warp-level bf16 mma.sync; row-pair tiles,
// 4px/thread float4 perception, k-split layer-2 (acc->A reuse),
// ch-pair-packed bf16x2 ds partials (sts32), ch-pair reduce.
// B=16,C=16,H=256,W=256, HID=128, OUT_C=13, perception K=48.
#define Cz     16
#define HID    128
#define OUTC   13
#define NPAIRS 2048
#define TPB    256
#define GRID   296
#define PCH    48

// ---- shared memory (bytes) ----
#define SM_PA  0            // P_A[48][256] bf16 swizzled 512B rows -> 24576
#define SM_PB  24576        // P_B                                   -> 24576
#define SM_DS  49152        // ds partials [4 kg][8 chpair][256 px] u32 -> 32768
#define SM_TOT 81920
// one-time weight staging overlaps DS (consumed before first DS write)
#define SM_W1T (SM_DS)              // W1t[48][128] bf16 256B rows (12288)
#define SM_W2T (SM_DS + 12288)      // W2t[128][16] bf16 32B rows   (4096)

typedef unsigned int u32;

__device__ __forceinline__ u32 smem_u32(const void* p) {
    u32 a;
    asm("{ .reg .u64 t; cvta.to.shared.u64 t, %1; cvt.u32.u64 %0, t; }"
        : "=r"(a) : "l"(p));
    return a;
}
__device__ __forceinline__ u32 bf2(float lo, float hi) {
    u32 r;  // first asm src -> upper half
    asm("cvt.rn.bf16x2.f32 %0, %1, %2;" : "=r"(r) : "f"(hi), "f"(lo));
    return r;
}
__device__ __forceinline__ void sts32(u32 a, u32 v) {
    asm volatile("st.shared.b32 [%0], %1;" :: "r"(a), "r"(v) : "memory");
}
__device__ __forceinline__ void sts64w(u32 a, u32 x, u32 y) {
    asm volatile("st.shared.v2.b32 [%0], {%1,%2};" :: "r"(a), "r"(x), "r"(y) : "memory");
}
__device__ __forceinline__ uint2 lds64u(u32 a) {
    uint2 r;
    asm volatile("ld.shared.v2.b32 {%0,%1}, [%2];" : "=r"(r.x), "=r"(r.y) : "r"(a));
    return r;
}
__device__ __forceinline__ void ldsm4t(u32* r, u32 a) {
    asm volatile("ldmatrix.sync.aligned.m8n8.x4.trans.shared.b16 {%0,%1,%2,%3}, [%4];"
        : "=r"(r[0]), "=r"(r[1]), "=r"(r[2]), "=r"(r[3]) : "r"(a));
}
__device__ __forceinline__ void ldsm2t(u32* r, u32 a) {
    asm volatile("ldmatrix.sync.aligned.m8n8.x2.trans.shared.b16 {%0,%1}, [%2];"
        : "=r"(r[0]), "=r"(r[1]) : "r"(a));
}
__device__ __forceinline__ void mma16816(float* d, const u32* a, const u32* b) {
    asm volatile(
        "mma.sync.aligned.m16n8k16.row.col.f32.bf16.bf16.f32 "
        "{%0,%1,%2,%3}, {%4,%5,%6,%7}, {%8,%9}, {%0,%1,%2,%3};"
        : "+f"(d[0]), "+f"(d[1]), "+f"(d[2]), "+f"(d[3])
        : "r"(a[0]), "r"(a[1]), "r"(a[2]), "r"(a[3]), "r"(b[0]), "r"(b[1]));
}

// P: bf16 [rows][256 px], 512B rows, XOR-swizzled 16B groups
__device__ __forceinline__ u32 p_off(int row, int px) {
    return (u32)(row * 512 + ((((px) >> 3) ^ (row & 7)) << 4) + ((px & 7) << 1));
}
// ds: u32 [4 kg][8 chpair][256 px]; bank-rotate by chpair
__device__ __forceinline__ u32 dsc_off(int cp, int px) {
    return (u32)(cp * 1024 + (((px) << 2) ^ ((cp & 7) << 5)));
}

__global__ __launch_bounds__(TPB, 2)
void GCA_mma7_kernel(const float* __restrict__ in, const float* __restrict__ w1,
                     const float* __restrict__ b1, const float* __restrict__ w2,
                     float* __restrict__ out)
{
    extern __shared__ char smem[];
    const u32 sb = smem_u32(smem);
    const int tid  = threadIdx.x;
    const int lane = tid & 31;
    const int q    = lane & 3;
    const int kg   = (tid >> 5) & 3;   // hidden k-group: cols 32*kg..32*kg+31
    const int wpx  = tid >> 7;         // px half within the row (warp>>2)

    // ---- stage transposed bf16 weights (overlaps DS; one-time) ----
    for (int i = tid; i < HID * PCH; i += TPB) {
        int n = i / PCH, k = i - n * PCH;
        *reinterpret_cast<__nv_bfloat16*>(smem + SM_W1T + k * 256 + n * 2) =
            __float2bfloat16(w1[i]);
    }
    for (int i = tid; i < HID * 16; i += TPB) {
        int k = i >> 4, n = i & 15;
        float v = (n < OUTC) ? w2[n * HID + k] : 0.0f;
        *reinterpret_cast<__nv_bfloat16*>(smem + SM_W2T + i * 2) =
            __float2bfloat16(v);
    }
    __syncthreads();

    // ---- persistent weight fragments + bias (per warp k-group) ----
    u32 fb1[4][3][2];
    u32 fb2[2][2][2];
    float bias[4][2];
#pragma unroll
    for (int j = 0; j < 4; ++j) {
#pragma unroll
        for (int kk = 0; kk < 3; ++kk)
            ldsm2t(fb1[j][kk],
                   sb + SM_W1T + (16 * kk + (lane & 15)) * 256 + (32 * kg + 8 * j) * 2);
        bias[j][0] = b1[32 * kg + 8 * j + 2 * q];
        bias[j][1] = b1[32 * kg + 8 * j + 2 * q + 1];
    }
#pragma unroll
    for (int kb = 0; kb < 2; ++kb)
#pragma unroll
        for (int n2 = 0; n2 < 2; ++n2)
            ldsm2t(fb2[kb][n2],
                   sb + SM_W2T + (32 * kg + 16 * kb + (lane & 15)) * 32 + 8 * n2 * 2);
    __syncthreads();      // weights consumed; DS region free

    const int lk = (lane & 7) + ((lane >> 4) << 3);
    const int lm = ((lane >> 3) & 1) << 3;
    const int l4 = lane >> 2;

    for (int pair = blockIdx.x; pair < NPAIRS; pair += GRID) {
        const int bimg = pair >> 7;
        const int y0   = (pair & 127) << 1;
        const float* bbase = in + ((size_t)bimg << 20);
        float* obase = out + ((size_t)bimg << 20);

        // ===== phase 1: perception — 4 px/thread, float4 centers =====
        {
            const int g  = tid >> 6;               // ch quad: 4g..4g+3
            const int x0 = (tid & 63) << 2;        // multiple of 4
            const int xm = (x0 - 1) & 255, x4 = (x0 + 4) & 255;
            const int rA = ((y0 - 1) & 255) << 8;
            const int rB = y0 << 8;
            const int rC = (y0 + 1) << 8;
            const int rD = ((y0 + 2) & 255) << 8;
#pragma unroll
            for (int c4 = 0; c4 < 4; ++c4) {
                const int ch = g * 4 + c4;
                const float* pc = bbase + (ch << 16);
                float4 vA = *reinterpret_cast<const float4*>(pc + rA + x0);
                float4 vB = *reinterpret_cast<const float4*>(pc + rB + x0);
                float4 vC = *reinterpret_cast<const float4*>(pc + rC + x0);
                float4 vD = *reinterpret_cast<const float4*>(pc + rD + x0);
                float aL = pc[rA + xm], aR = pc[rA + x4];
                float bL = pc[rB + xm], bR = pc[rB + x4];
                float cL = pc[rC + xm], cR = pc[rC + x4];
                float dL = pc[rD + xm], dR = pc[rD + x4];

                // horizontal central differences per row
                float DA0 = vA.y - aL,  DA1 = vA.z - vA.x,
                      DA2 = vA.w - vA.y, DA3 = aR - vA.z;
                float DB0 = vB.y - bL,  DB1 = vB.z - vB.x,
                      DB2 = vB.w - vB.y, DB3 = bR - vB.z;
                float DC0 = vC.y - cL,  DC1 = vC.z - vC.x,
                      DC2 = vC.w - vC.y, DC3 = cR - vC.z;
                float DD0 = vD.y - dL,  DD1 = vD.z - vD.x,
                      DD2 = vD.w - vD.y, DD3 = dR - vD.z;
                // horizontal smoothing sums per row
                float SA0 = aL + 2.f*vA.x + vA.y, SA1 = vA.x + 2.f*vA.y + vA.z,
                      SA2 = vA.y + 2.f*vA.z + vA.w, SA3 = vA.z + 2.f*vA.w + aR;
                float SB0 = bL + 2.f*vB.x + vB.y, SB1 = vB.x + 2.f*vB.y + vB.z,
                      SB2 = vB.y + 2.f*vB.z + vB.w, SB3 = vB.z + 2.f*vB.w + bR;
                float SC0 = cL + 2.f*vC.x + vC.y, SC1 = vC.x + 2.f*vC.y + vC.z,
                      SC2 = vC.y + 2.f*vC.z + vC.w, SC3 = vC.z + 2.f*vC.w + cR;
                float SD0 = dL + 2.f*vD.x + vD.y, SD1 = vD.x + 2.f*vD.y + vD.z,
                      SD2 = vD.y + 2.f*vD.z + vD.w, SD3 = vD.z + 2.f*vD.w + dR;

                // row y0: gx = DA+2DB+DC, gy = SC-SA ; id = vB
                sts64w(sb + SM_PA + p_off(ch, x0),
                       bf2(vB.x, vB.y), bf2(vB.z, vB.w));
                sts64w(sb + SM_PA + p_off(Cz + ch, x0),
                       bf2(DA0 + 2.f*DB0 + DC0, DA1 + 2.f*DB1 + DC1),
                       bf2(DA2 + 2.f*DB2 + DC2, DA3 + 2.f*DB3 + DC3));
                sts64w(sb + SM_PA + p_off(2 * Cz + ch, x0),
                       bf2(SC0 - SA0, SC1 - SA1), bf2(SC2 - SA2, SC3 - SA3));

                // row y0+1: gx = DB+2DC+DD, gy = SD-SB ; id = vC
                sts64w(sb + SM_PB + p_off(ch, x0),
                       bf2(vC.x, vC.y), bf2(vC.z, vC.w));
                sts64w(sb + SM_PB + p_off(Cz + ch, x0),
                       bf2(DB0 + 2.f*DC0 + DD0, DB1 + 2.f*DC1 + DD1),
                       bf2(DB2 + 2.f*DC2 + DD2, DB3 + 2.f*DC3 + DD3));
                sts64w(sb + SM_PB + p_off(2 * Cz + ch, x0),
                       bf2(SD0 - SB0, SD1 - SB1), bf2(SD2 - SB2, SD3 - SB3));

                if (ch < 3) {                      // exact state copy, both rows
                    *reinterpret_cast<float4*>(obase + (ch << 16) + rB + x0) = vB;
                    *reinterpret_cast<float4*>(obase + (ch << 16) + rC + x0) = vC;
                }
            }
        }
        __syncthreads();

        // ===== phases 2-4 for each row of the pair =====
#pragma unroll 1
        for (int rs = 0; rs < 2; ++rs) {
            const u32 pb = sb + (rs ? SM_PB : SM_PA);
            const int r0 = (y0 + rs) << 8;

            // ---- fused MLP, k-split layer-2 ----
#pragma unroll 2
            for (int mt = 0; mt < 8; ++mt) {
                const int pxb = 128 * wpx + 16 * mt;
                u32 a[3][4];
#pragma unroll
                for (int kk = 0; kk < 3; ++kk) {
                    int krow = 16 * kk + lk;
                    int pxc  = pxb + lm;
                    ldsm4t(a[kk], pb + (u32)(krow * 512 +
                           (((pxc >> 3) ^ (krow & 7)) << 4)));
                }

                // layer-1: 4 n-tiles -> bias+ReLU -> bf16 A-frags
                u32 a2f[2][4];
#pragma unroll
                for (int j = 0; j < 4; ++j) {
                    float c[4] = {0.f, 0.f, 0.f, 0.f};
#pragma unroll
                    for (int kk = 0; kk < 3; ++kk) mma16816(c, a[kk], fb1[j][kk]);
                    float h0 = fmaxf(c[0] + bias[j][0], 0.f);
                    float h1 = fmaxf(c[1] + bias[j][1], 0.f);
                    float h2 = fmaxf(c[2] + bias[j][0], 0.f);
                    float h3 = fmaxf(c[3] + bias[j][1], 0.f);
                    a2f[j >> 1][(j & 1) * 2]     = bf2(h0, h1);
                    a2f[j >> 1][(j & 1) * 2 + 1] = bf2(h2, h3);
                }

                // layer-2 partial over this warp's 32 hidden channels
                float c2[2][4] = {{0.f,0.f,0.f,0.f},{0.f,0.f,0.f,0.f}};
#pragma unroll
                for (int kb = 0; kb < 2; ++kb) {
                    mma16816(c2[0], a2f[kb], fb2[kb][0]);
                    mma16816(c2[1], a2f[kb], fb2[kb][1]);
                }

                // ds partial: ch-pair packed bf16x2, 4 sts32
                const u32 dsb = sb + SM_DS + (u32)kg * 8192u;
#pragma unroll
                for (int n2 = 0; n2 < 2; ++n2) {
                    const int cp = 4 * n2 + q;
#pragma unroll
                    for (int hf = 0; hf < 2; ++hf) {
                        int px = pxb + hf * 8 + l4;
                        sts32(dsb + dsc_off(cp, px),
                              bf2(c2[n2][hf * 2], c2[n2][hf * 2 + 1]));
                    }
                }
            }
            __syncthreads();

            // ---- reduce 4 kg partials (ch-pair words) + residual ----
            {
                const int px0 = (tid & 127) << 1;
                const int cpa = (tid < 128) ? 0 : 4;
                const int cpe = (tid < 128) ? 4 : 7;
                for (int cp = cpa; cp < cpe; ++cp) {
                    const int chL = 3 + 2 * cp;         // 3,5,..,15
                    const int chH = chL + 1;
                    float2 sL = *reinterpret_cast<const float2*>(
                        bbase + (chL << 16) + r0 + px0);
                    float2 sH = make_float2(0.f, 0.f);
                    if (chH < 16)
                        sH = *reinterpret_cast<const float2*>(
                            bbase + (chH << 16) + r0 + px0);
                    const u32 base = sb + SM_DS + dsc_off(cp, px0);
#pragma unroll
                    for (int g = 0; g < 4; ++g) {
                        uint2 w = lds64u(base + (u32)g * 8192u);
                        sL.x += __uint_as_float(w.x << 16);
                        sH.x += __uint_as_float(w.x & 0xFFFF0000u);
                        sL.y += __uint_as_float(w.y << 16);
                        sH.y += __uint_as_float(w.y & 0xFFFF0000u);
                    }
                    *reinterpret_cast<float2*>(obase + (chL << 16) + r0 + px0) = sL;
                    if (chH < 16)
                        *reinterpret_cast<float2*>(
                            obase + (chH << 16) + r0 + px0) = sH;
                }
            }
            __syncthreads();
        }
    }
}

extern "C" void kernel_launch(void* const* d_in, const int* in_sizes, int n_in,
                              void* d_out, int out_size)
{
    const float* in = (const float*)d_in[0];
    const float* w1 = (const float*)d_in[1];
    const float* b1 = (const float*)d_in[2];
    const float* w2 = (const float*)d_in[3];
    float* out = (float*)d_out;

    cudaFuncSetAttribute(GCA_mma7_kernel,
                         cudaFuncAttributeMaxDynamicSharedMemorySize, SM_TOT);
    GCA_mma7_kernel<<<GRID, TPB, SM_TOT>>>(in, w1, b1, w2, out);
}